// round 2
// baseline (speedup 1.0000x reference)
#include <cuda_runtime.h>
#include <cstdint>

#define T_    4
#define B_    32
#define C_    384
#define HID_  1536
#define HW_   196
#define NPAIR (B_*HW_)        // 6272 (b,hw) pairs
#define NROW  (NPAIR*T_)      // 25088 rows of GEMM1
#define CW_   (C_/32)         // 12 bitmask words per row
#define SPIKE_CAP (1u<<22)

#define PG 64                 // pairs per CTA-group in fused kernel
#define RPG (PG*T_)           // 256 rows per group
#define ON 128                // output-channel chunk
#define NCH (HID_/ON)         // 12
#define NG  (NPAIR/PG)        // 98
#define GSPLIT 13             // CTAs along group axis (each loops ~8 groups)
#define LCAP 64               // staged list entries per row (overflow -> global)

// smem layout for fused kernel
#define SMEM_W_BYTES   (C_*ON*4)            // 196608
#define SMEM_L_BYTES   (RPG*LCAP*2)         // 32768
#define SMEM_C_BYTES   (RPG*4)              // 1024
#define SMEM_TOTAL     (SMEM_W_BYTES + SMEM_L_BYTES + SMEM_C_BYTES)

// ---- scratch (static device allocations; no cudaMalloc anywhere) ----
__device__ float          g_w1t[C_*HID_];          // [c][o]
__device__ float          g_w2t[HID_*C_];          // [c][o]
__device__ unsigned       g_smask[NROW*CW_];       // s1 bitmasks
__device__ unsigned short g_list[(size_t)NROW*C_]; // per-row active-c lists
__device__ int            g_cnt[NROW];
__device__ unsigned       g_spikes[SPIKE_CAP];
__device__ unsigned       g_nspk;

// ---------------- K0: 32x32 tiled transpose ----------------
__global__ void k_transpose(const float* __restrict__ in, float* __restrict__ outp,
                            int rows, int cols) {
    __shared__ float tile[32][33];
    int bx = blockIdx.x * 32, by = blockIdx.y * 32;
    int x = bx + threadIdx.x;
    #pragma unroll
    for (int k = 0; k < 32; k += 8) {
        int y = by + threadIdx.y + k;
        if (x < cols && y < rows)
            tile[threadIdx.y + k][threadIdx.x] = in[(size_t)y*cols + x];
    }
    __syncthreads();
    int xo = by + threadIdx.x;
    #pragma unroll
    for (int k = 0; k < 32; k += 8) {
        int yo = bx + threadIdx.y + k;
        if (xo < rows && yo < cols)
            outp[(size_t)yo*rows + xo] = tile[threadIdx.x][threadIdx.y + k];
    }
}

// ---------------- K1: PLIF1 -> spike bitmasks ----------------
__global__ void k_plif1(const float* __restrict__ x, const float* __restrict__ pw1) {
    int tid = blockIdx.x * blockDim.x + threadIdx.x;
    if (tid == 0) g_nspk = 0u;
    if (tid >= CW_ * NPAIR) return;
    int pair = tid % NPAIR;
    int cw   = tid / NPAIR;
    int b = pair / HW_, hw = pair % HW_;
    float decay = 1.0f / (1.0f + expf(-pw1[0]));

    unsigned bits[T_] = {0u, 0u, 0u, 0u};
    #pragma unroll 4
    for (int j = 0; j < 32; j++) {
        int c = cw * 32 + j;
        const float* xp = x + ((size_t)b * C_ + c) * HW_ + hw;
        float x0 = __ldg(xp);
        float x1 = __ldg(xp + (size_t)1*B_*C_*HW_);
        float x2 = __ldg(xp + (size_t)2*B_*C_*HW_);
        float x3 = __ldg(xp + (size_t)3*B_*C_*HW_);
        float v = 0.f, h;
        h = v + (x0 - v) * decay; if (h >= 1.0f) { bits[0] |= 1u << j; v = 0.f; } else v = h;
        h = v + (x1 - v) * decay; if (h >= 1.0f) { bits[1] |= 1u << j; v = 0.f; } else v = h;
        h = v + (x2 - v) * decay; if (h >= 1.0f) { bits[2] |= 1u << j; v = 0.f; } else v = h;
        h = v + (x3 - v) * decay; if (h >= 1.0f) { bits[3] |= 1u << j; v = 0.f; } else v = h;
    }
    int rbase = pair * T_;
    #pragma unroll
    for (int t = 0; t < T_; t++)
        g_smask[(rbase + t) * CW_ + cw] = bits[t];
}

// ---------------- K2: bitmask -> ordered active-channel lists ----------------
__global__ void k_listbuild() {
    int wrow = (blockIdx.x * blockDim.x + threadIdx.x) >> 5;
    int lane = threadIdx.x & 31;
    if (wrow >= NROW) return;
    unsigned short* lp = g_list + (size_t)wrow * C_;
    int base = 0;
    #pragma unroll
    for (int w = 0; w < CW_; w++) {
        unsigned word = g_smask[wrow * CW_ + w];
        if ((word >> lane) & 1u) {
            int pre = __popc(word & ((1u << lane) - 1u));
            lp[base + pre] = (unsigned short)(w * 32 + lane);
        }
        base += __popc(word);
    }
    if (lane == 0) g_cnt[wrow] = base;
}

// ---------------- K3: fused sparse GEMM1 + PLIF2 -> spike list ----------------
__device__ __forceinline__ void plif2_comp(float a, float bb, float& v, float decay,
                                           int t, int b, int hw, int o) {
    float xx = a + bb;
    float h = v + (xx - v) * decay;
    if (h >= 1.0f) {
        unsigned pos = atomicAdd(&g_nspk, 1u);
        if (pos < SPIKE_CAP)
            g_spikes[pos] = (unsigned)((((t * B_ + b) * HID_) + o) * HW_ + hw);
        v = 0.f;
    } else {
        v = h;
    }
}

__global__ __launch_bounds__(512, 1)
void k_gemm1_plif2(const float* __restrict__ pw2, const float* __restrict__ b1) {
    extern __shared__ char smem_raw[];
    float*          ws    = (float*)smem_raw;                             // [C_][ON]
    unsigned short* slist = (unsigned short*)(smem_raw + SMEM_W_BYTES);   // [RPG][LCAP]
    int*            scnt  = (int*)(smem_raw + SMEM_W_BYTES + SMEM_L_BYTES);

    const int chunk = blockIdx.x;              // 0..NCH-1
    const int tid   = threadIdx.x;
    const int warp  = tid >> 5, oq = tid & 31;

    // stage w1t[:, chunk*ON : +ON] into smem once per CTA
    const float* w1tp = g_w1t + chunk * ON;
    for (int i = tid; i < C_ * (ON/4); i += 512) {
        int c  = i >> 5;                       // ON/4 = 32
        int o4 = i & 31;
        ((float4*)ws)[i] = __ldg((const float4*)(w1tp + (size_t)c * HID_) + o4);
    }

    const float decay = 1.0f / (1.0f + expf(-pw2[0]));
    const float4 b1v = __ldg((const float4*)(b1 + chunk * ON) + oq);
    const int obase = chunk * ON + oq * 4;
    const float4* ws4 = (const float4*)ws;

    for (int g = blockIdx.y; g < NG; g += GSPLIT) {
        const int row0 = g * RPG;              // first global row of this group
        __syncthreads();                       // weights staged / prev compute done

        // stage lists: 256 rows x 64 entries (128B/row) via uint4
        {
            const uint4* gl4 = (const uint4*)(g_list + (size_t)row0 * C_);
            uint4*       sl4 = (uint4*)slist;
            // global row stride in uint4 = 384*2/16 = 48 ; smem row stride = 8
            for (int i = tid; i < RPG * 8; i += 512) {
                int lr = i >> 3, q = i & 7;
                sl4[lr * 8 + q] = gl4[(size_t)lr * 48 + q];
            }
            if (tid < RPG) scnt[tid] = g_cnt[row0 + tid];
        }
        __syncthreads();

        float4 acc[4][T_];
        #pragma unroll
        for (int p = 0; p < 4; p++)
            #pragma unroll
            for (int t = 0; t < T_; t++) acc[p][t] = make_float4(0.f, 0.f, 0.f, 0.f);

        #pragma unroll
        for (int p = 0; p < 4; p++) {
            const int lpair = warp * 4 + p;
            #pragma unroll
            for (int t = 0; t < T_; t++) {
                const int lr = lpair * T_ + t;
                const int n = scnt[lr];
                const unsigned short* lp = slist + lr * LCAP;
                float4 a = acc[p][t];
                int i = 0;
                int nn = n < LCAP ? n : LCAP;
                for (; i + 4 <= nn; i += 4) {
                    ushort4 cc = *(const ushort4*)(lp + i);
                    float4 v0 = ws4[cc.x * 32 + oq];
                    float4 v1 = ws4[cc.y * 32 + oq];
                    float4 v2 = ws4[cc.z * 32 + oq];
                    float4 v3 = ws4[cc.w * 32 + oq];
                    a.x += v0.x; a.y += v0.y; a.z += v0.z; a.w += v0.w;
                    a.x += v1.x; a.y += v1.y; a.z += v1.z; a.w += v1.w;
                    a.x += v2.x; a.y += v2.y; a.z += v2.z; a.w += v2.w;
                    a.x += v3.x; a.y += v3.y; a.z += v3.z; a.w += v3.w;
                }
                for (; i < nn; i++) {
                    float4 v0 = ws4[(int)lp[i] * 32 + oq];
                    a.x += v0.x; a.y += v0.y; a.z += v0.z; a.w += v0.w;
                }
                // rare overflow beyond LCAP: finish from global list
                if (n > LCAP) {
                    const unsigned short* gp = g_list + (size_t)(row0 + lr) * C_;
                    for (int j = LCAP; j < n; j++) {
                        float4 v0 = ws4[(int)gp[j] * 32 + oq];
                        a.x += v0.x; a.y += v0.y; a.z += v0.z; a.w += v0.w;
                    }
                }
                acc[p][t] = a;
            }
        }

        // epilogue: PLIF2 across t (exact fp32), emit rare spikes
        #pragma unroll
        for (int p = 0; p < 4; p++) {
            const int pair = g * PG + warp * 4 + p;
            const int b = pair / HW_, hw = pair % HW_;
            float vx = 0.f, vy = 0.f, vz = 0.f, vw = 0.f;
            #pragma unroll
            for (int t = 0; t < T_; t++) {
                plif2_comp(acc[p][t].x, b1v.x, vx, decay, t, b, hw, obase + 0);
                plif2_comp(acc[p][t].y, b1v.y, vy, decay, t, b, hw, obase + 1);
                plif2_comp(acc[p][t].z, b1v.z, vz, decay, t, b, hw, obase + 2);
                plif2_comp(acc[p][t].w, b1v.w, vw, decay, t, b, hw, obase + 3);
            }
        }
    }
}

// ---------------- K4: out = b2 (broadcast fill) ----------------
__global__ void k_outinit(float* __restrict__ out, const float* __restrict__ b2) {
    int i = blockIdx.x * blockDim.x + threadIdx.x;   // float4 index
    const int total4 = T_ * B_ * C_ * HW_ / 4;
    if (i >= total4) return;
    int o = (i / (HW_ / 4)) % C_;
    float bv = __ldg(b2 + o);
    ((float4*)out)[i] = make_float4(bv, bv, bv, bv);
}

// ---------------- K5: scatter spikes -> out += w2t column ----------------
__global__ void k_scatter(float* __restrict__ out) {
    unsigned n = *(volatile unsigned*)&g_nspk;
    if (n > SPIKE_CAP) n = SPIKE_CAP;
    int wid  = (blockIdx.x * blockDim.x + threadIdx.x) >> 5;
    int lane = threadIdx.x & 31;
    int nw   = (gridDim.x * blockDim.x) >> 5;
    for (unsigned s = wid; s < n; s += nw) {
        unsigned lin = g_spikes[s];
        unsigned hw = lin % HW_;
        unsigned r  = lin / HW_;
        unsigned c  = r % HID_;
        unsigned tb = r / HID_;
        const float* wcol = g_w2t + (size_t)c * C_;
        float* op = out + (size_t)tb * C_ * HW_ + hw;
        for (int o = lane; o < C_; o += 32)
            atomicAdd(op + (size_t)o * HW_, wcol[o]);
    }
}

// ---------------- launch ----------------
extern "C" void kernel_launch(void* const* d_in, const int* in_sizes, int n_in,
                              void* d_out, int out_size) {
    const float* x   = (const float*)d_in[0];
    const float* pw1 = (const float*)d_in[1];
    const float* w1  = (const float*)d_in[2];
    const float* b1  = (const float*)d_in[3];
    const float* pw2 = (const float*)d_in[4];
    const float* w2  = (const float*)d_in[5];
    const float* b2  = (const float*)d_in[6];
    float* out = (float*)d_out;

    (void)in_sizes; (void)n_in; (void)out_size;

    cudaFuncSetAttribute(k_gemm1_plif2,
                         cudaFuncAttributeMaxDynamicSharedMemorySize, SMEM_TOTAL);

    float* w1t; cudaGetSymbolAddress((void**)&w1t, g_w1t);
    float* w2t; cudaGetSymbolAddress((void**)&w2t, g_w2t);

    {   // w1 [HID_,C_] -> w1t [C_,HID_]
        dim3 blk(32, 8), grd(C_ / 32, HID_ / 32);
        k_transpose<<<grd, blk>>>(w1, w1t, HID_, C_);
    }
    {   // w2 [C_,HID_] -> w2t [HID_,C_]
        dim3 blk(32, 8), grd(HID_ / 32, C_ / 32);
        k_transpose<<<grd, blk>>>(w2, w2t, C_, HID_);
    }

    k_plif1<<<(CW_ * NPAIR + 255) / 256, 256>>>(x, pw1);
    k_listbuild<<<(NROW * 32 + 255) / 256, 256>>>();

    dim3 g2(NCH, GSPLIT);
    k_gemm1_plif2<<<g2, 512, SMEM_TOTAL>>>(pw2, b1);

    k_outinit<<<(T_ * B_ * C_ * HW_ / 4 + 255) / 256, 256>>>(out, b2);
    k_scatter<<<256, 256>>>(out);
}

// round 3
// speedup vs baseline: 3.0087x; 3.0087x over previous
#include <cuda_runtime.h>
#include <cstdint>

#define T_    4
#define B_    32
#define C_    384
#define HID_  1536
#define HW_   196
#define NPAIR (B_*HW_)        // 6272 (b,hw) pairs
#define NROW  (NPAIR*T_)      // 25088 rows of GEMM1
#define CW_   (C_/32)         // 12 bitmask words per row
#define SPIKE_CAP (1u<<22)

#define PG 64                 // pairs per group
#define RPG (PG*T_)           // 256 rows per group
#define ON 128                // output-channel chunk
#define NCH (HID_/ON)         // 12
#define NG  (NPAIR/PG)        // 98
#define GSPLIT 12             // 12x12 = 144 CTAs = one wave on 148 SMs
#define LCAP 64               // staged list entries per row

#define SMEM_W_BYTES   (C_*ON*4)            // 196608
#define SMEM_L_BYTES   (RPG*LCAP*2)         // 32768
#define SMEM_C_BYTES   (RPG*4)              // 1024
#define SMEM_TOTAL     (SMEM_W_BYTES + SMEM_L_BYTES + SMEM_C_BYTES)  // 230400

// ---- scratch (static device allocations) ----
__device__ float          g_w1t[C_*HID_];
__device__ float          g_w2t[HID_*C_];
__device__ unsigned       g_smask[NROW*CW_];
__device__ unsigned short g_list[(size_t)NROW*C_];
__device__ int            g_cnt[NROW];
__device__ unsigned       g_spikes[SPIKE_CAP];
__device__ unsigned       g_nspk;

// ---------------- K0: 32x32 tiled transpose ----------------
__global__ void k_transpose(const float* __restrict__ in, float* __restrict__ outp,
                            int rows, int cols) {
    __shared__ float tile[32][33];
    int bx = blockIdx.x * 32, by = blockIdx.y * 32;
    int x = bx + threadIdx.x;
    #pragma unroll
    for (int k = 0; k < 32; k += 8) {
        int y = by + threadIdx.y + k;
        if (x < cols && y < rows)
            tile[threadIdx.y + k][threadIdx.x] = in[(size_t)y*cols + x];
    }
    __syncthreads();
    int xo = by + threadIdx.x;
    #pragma unroll
    for (int k = 0; k < 32; k += 8) {
        int yo = bx + threadIdx.y + k;
        if (xo < rows && yo < cols)
            outp[(size_t)yo*rows + xo] = tile[threadIdx.x][threadIdx.y + k];
    }
}

// ---------------- K1: PLIF1 -> spike bitmasks ----------------
__global__ void k_plif1(const float* __restrict__ x, const float* __restrict__ pw1) {
    int tid = blockIdx.x * blockDim.x + threadIdx.x;
    if (tid == 0) g_nspk = 0u;
    if (tid >= CW_ * NPAIR) return;
    int pair = tid % NPAIR;
    int cw   = tid / NPAIR;
    int b = pair / HW_, hw = pair % HW_;
    float decay = 1.0f / (1.0f + expf(-pw1[0]));

    unsigned bits[T_] = {0u, 0u, 0u, 0u};
    #pragma unroll 4
    for (int j = 0; j < 32; j++) {
        int c = cw * 32 + j;
        const float* xp = x + ((size_t)b * C_ + c) * HW_ + hw;
        float x0 = __ldg(xp);
        float x1 = __ldg(xp + (size_t)1*B_*C_*HW_);
        float x2 = __ldg(xp + (size_t)2*B_*C_*HW_);
        float x3 = __ldg(xp + (size_t)3*B_*C_*HW_);
        float v = 0.f, h;
        h = v + (x0 - v) * decay; if (h >= 1.0f) { bits[0] |= 1u << j; v = 0.f; } else v = h;
        h = v + (x1 - v) * decay; if (h >= 1.0f) { bits[1] |= 1u << j; v = 0.f; } else v = h;
        h = v + (x2 - v) * decay; if (h >= 1.0f) { bits[2] |= 1u << j; v = 0.f; } else v = h;
        h = v + (x3 - v) * decay; if (h >= 1.0f) { bits[3] |= 1u << j; v = 0.f; } else v = h;
    }
    int rbase = pair * T_;
    #pragma unroll
    for (int t = 0; t < T_; t++)
        g_smask[(rbase + t) * CW_ + cw] = bits[t];
}

// ---------------- K2: bitmask -> ordered active-channel lists ----------------
__global__ void k_listbuild() {
    int wrow = (blockIdx.x * blockDim.x + threadIdx.x) >> 5;
    int lane = threadIdx.x & 31;
    if (wrow >= NROW) return;
    unsigned short* lp = g_list + (size_t)wrow * C_;
    int base = 0;
    #pragma unroll
    for (int w = 0; w < CW_; w++) {
        unsigned word = g_smask[wrow * CW_ + w];
        if ((word >> lane) & 1u) {
            int pre = __popc(word & ((1u << lane) - 1u));
            lp[base + pre] = (unsigned short)(w * 32 + lane);
        }
        base += __popc(word);
    }
    if (lane == 0) g_cnt[wrow] = base;
}

// ---------------- K3: fused sparse GEMM1 + PLIF2 ----------------
__device__ __forceinline__ void plif2_comp(float a, float bb, float& v, float decay,
                                           int t, int b, int hw, int o) {
    float xx = a + bb;
    float h = v + (xx - v) * decay;
    if (h >= 1.0f) {
        unsigned pos = atomicAdd(&g_nspk, 1u);
        if (pos < SPIKE_CAP)
            g_spikes[pos] = (unsigned)((((t * B_ + b) * HID_) + o) * HW_ + hw);
        v = 0.f;
    } else {
        v = h;
    }
}

__device__ __forceinline__ void lds_v2u64(unsigned addr, unsigned long long& a,
                                          unsigned long long& b) {
    asm("ld.shared.v2.u64 {%0,%1},[%2];" : "=l"(a), "=l"(b) : "r"(addr));
}
__device__ __forceinline__ void addx2(unsigned long long& a, unsigned long long v) {
    asm("add.rn.f32x2 %0, %0, %1;" : "+l"(a) : "l"(v));
}

__global__ __launch_bounds__(1024, 1)
void k_gemm1_plif2(const float* __restrict__ pw2, const float* __restrict__ b1) {
    extern __shared__ char smem_raw[];
    float*          ws    = (float*)smem_raw;                             // [C_][ON]
    unsigned short* slist = (unsigned short*)(smem_raw + SMEM_W_BYTES);   // [RPG][LCAP]
    int*            scnt  = (int*)(smem_raw + SMEM_W_BYTES + SMEM_L_BYTES);

    const int chunk = blockIdx.x;              // 0..NCH-1
    const int tid   = threadIdx.x;
    const int warp  = tid >> 5, oq = tid & 31;

    // stage w1t[:, chunk*ON : +ON] once per CTA
    const float* w1tp = g_w1t + chunk * ON;
    for (int i = tid; i < C_ * (ON/4); i += 1024) {
        int c  = i >> 5;
        int o4 = i & 31;
        ((float4*)ws)[i] = __ldg((const float4*)(w1tp + (size_t)c * HID_) + o4);
    }

    const unsigned wbase = (unsigned)__cvta_generic_to_shared(ws) + oq * 16u;
    const float decay = 1.0f / (1.0f + expf(-pw2[0]));
    const float4 b1v = __ldg((const float4*)(b1 + chunk * ON) + oq);
    const int obase = chunk * ON + oq * 4;

    for (int g = blockIdx.y; g < NG; g += GSPLIT) {
        const int row0 = g * RPG;
        __syncthreads();                       // prev compute done / weights staged

        {   // stage 256 rows x 64 entries (128B/row) of lists + counts
            const uint4* gl4 = (const uint4*)(g_list + (size_t)row0 * C_);
            uint4*       sl4 = (uint4*)slist;
            #pragma unroll
            for (int i = tid; i < RPG * (LCAP/8); i += 1024)
                sl4[i] = gl4[(size_t)(i >> 3) * (C_/8) + (i & 7)];
            if (tid < RPG) scnt[tid] = g_cnt[row0 + tid];
        }
        __syncthreads();

        #pragma unroll
        for (int p = 0; p < 2; p++) {
            const int lpair = warp * 2 + p;
            const int pair  = g * PG + lpair;
            unsigned long long a01[T_], a23[T_];
            #pragma unroll
            for (int t = 0; t < T_; t++) { a01[t] = 0ull; a23[t] = 0ull; }

            #pragma unroll
            for (int t = 0; t < T_; t++) {
                const int lr = lpair * T_ + t;
                const int n  = scnt[lr];
                const unsigned short* lp = slist + lr * LCAP;
                unsigned long long s01 = a01[t], s23 = a23[t];
                const int nn = n < LCAP ? n : LCAP;
                int i = 0;
                for (; i + 4 <= nn; i += 4) {
                    ushort4 cc = *(const ushort4*)(lp + i);
                    unsigned long long v0a, v0b, v1a, v1b, v2a, v2b, v3a, v3b;
                    lds_v2u64(wbase + (unsigned)cc.x * 512u, v0a, v0b);
                    lds_v2u64(wbase + (unsigned)cc.y * 512u, v1a, v1b);
                    lds_v2u64(wbase + (unsigned)cc.z * 512u, v2a, v2b);
                    lds_v2u64(wbase + (unsigned)cc.w * 512u, v3a, v3b);
                    addx2(s01, v0a); addx2(s23, v0b);
                    addx2(s01, v1a); addx2(s23, v1b);
                    addx2(s01, v2a); addx2(s23, v2b);
                    addx2(s01, v3a); addx2(s23, v3b);
                }
                for (; i < nn; i++) {
                    unsigned long long va, vb;
                    lds_v2u64(wbase + (unsigned)lp[i] * 512u, va, vb);
                    addx2(s01, va); addx2(s23, vb);
                }
                if (n > LCAP) {   // extremely rare tail from global list
                    const unsigned short* gp = g_list + (size_t)(row0 + lr) * C_;
                    for (int j = LCAP; j < n; j++) {
                        unsigned long long va, vb;
                        lds_v2u64(wbase + (unsigned)gp[j] * 512u, va, vb);
                        addx2(s01, va); addx2(s23, vb);
                    }
                }
                a01[t] = s01; a23[t] = s23;
            }

            // PLIF2 epilogue (exact fp32), emit rare spikes
            const int b = pair / HW_, hw = pair % HW_;
            float vx = 0.f, vy = 0.f, vz = 0.f, vw = 0.f;
            #pragma unroll
            for (int t = 0; t < T_; t++) {
                float fx = __uint_as_float((unsigned)(a01[t] & 0xffffffffull));
                float fy = __uint_as_float((unsigned)(a01[t] >> 32));
                float fz = __uint_as_float((unsigned)(a23[t] & 0xffffffffull));
                float fw = __uint_as_float((unsigned)(a23[t] >> 32));
                plif2_comp(fx, b1v.x, vx, decay, t, b, hw, obase + 0);
                plif2_comp(fy, b1v.y, vy, decay, t, b, hw, obase + 1);
                plif2_comp(fz, b1v.z, vz, decay, t, b, hw, obase + 2);
                plif2_comp(fw, b1v.w, vw, decay, t, b, hw, obase + 3);
            }
        }
    }
}

// ---------------- K4: out = b2 (broadcast fill) ----------------
__global__ void k_outinit(float* __restrict__ out, const float* __restrict__ b2) {
    int i = blockIdx.x * blockDim.x + threadIdx.x;
    const int total4 = T_ * B_ * C_ * HW_ / 4;
    if (i >= total4) return;
    int o = (i / (HW_ / 4)) % C_;
    float bv = __ldg(b2 + o);
    ((float4*)out)[i] = make_float4(bv, bv, bv, bv);
}

// ---------------- K5: scatter spikes -> out += w2t column ----------------
__global__ void k_scatter(float* __restrict__ out) {
    unsigned n = *(volatile unsigned*)&g_nspk;
    if (n > SPIKE_CAP) n = SPIKE_CAP;
    int wid  = (blockIdx.x * blockDim.x + threadIdx.x) >> 5;
    int lane = threadIdx.x & 31;
    int nw   = (gridDim.x * blockDim.x) >> 5;
    for (unsigned s = wid; s < n; s += nw) {
        unsigned lin = g_spikes[s];
        unsigned hw = lin % HW_;
        unsigned r  = lin / HW_;
        unsigned c  = r % HID_;
        unsigned tb = r / HID_;
        const float* wcol = g_w2t + (size_t)c * C_;
        float* op = out + (size_t)tb * C_ * HW_ + hw;
        for (int o = lane; o < C_; o += 32)
            atomicAdd(op + (size_t)o * HW_, wcol[o]);
    }
}

// ---------------- launch ----------------
extern "C" void kernel_launch(void* const* d_in, const int* in_sizes, int n_in,
                              void* d_out, int out_size) {
    const float* x   = (const float*)d_in[0];
    const float* pw1 = (const float*)d_in[1];
    const float* w1  = (const float*)d_in[2];
    const float* b1  = (const float*)d_in[3];
    const float* pw2 = (const float*)d_in[4];
    const float* w2  = (const float*)d_in[5];
    const float* b2  = (const float*)d_in[6];
    float* out = (float*)d_out;

    (void)in_sizes; (void)n_in; (void)out_size;

    cudaFuncSetAttribute(k_gemm1_plif2,
                         cudaFuncAttributeMaxDynamicSharedMemorySize, SMEM_TOTAL);

    float* w1t; cudaGetSymbolAddress((void**)&w1t, g_w1t);
    float* w2t; cudaGetSymbolAddress((void**)&w2t, g_w2t);

    {
        dim3 blk(32, 8), grd(C_ / 32, HID_ / 32);
        k_transpose<<<grd, blk>>>(w1, w1t, HID_, C_);
    }
    {
        dim3 blk(32, 8), grd(HID_ / 32, C_ / 32);
        k_transpose<<<grd, blk>>>(w2, w2t, C_, HID_);
    }

    k_plif1<<<(CW_ * NPAIR + 255) / 256, 256>>>(x, pw1);
    k_listbuild<<<(NROW * 32 + 255) / 256, 256>>>();

    dim3 g2(NCH, GSPLIT);
    k_gemm1_plif2<<<g2, 1024, SMEM_TOTAL>>>(pw2, b1);

    k_outinit<<<(T_ * B_ * C_ * HW_ / 4 + 255) / 256, 256>>>(out, b2);
    k_scatter<<<256, 256>>>(out);
}